// round 1
// baseline (speedup 1.0000x reference)
#include <cuda_runtime.h>
#include <math.h>

#define C_DIM 6625
#define D_DIM 96
#define N_ROWS 8192
#define EPS_F 1e-7f
#define BLOCK_T 256

// Per-row clipped loss scratch (no dynamic allocation allowed).
__device__ float g_row_loss[N_ROWS];

__global__ void __launch_bounds__(BLOCK_T)
center_loss_row_kernel(const float* __restrict__ features,
                       const float* __restrict__ predicts,
                       const float* __restrict__ centers) {
    const int row = blockIdx.x;
    const int tid = threadIdx.x;
    const float* __restrict__ p = predicts + (size_t)row * C_DIM;

    // ---- argmax over C (first-index tie-break) ----
    float best = -INFINITY;
    int bidx = 0x7fffffff;
    #pragma unroll 4
    for (int c = tid; c < C_DIM; c += BLOCK_T) {
        float v = __ldg(p + c);
        // strict > keeps the first (lowest-index) occurrence within this thread's stride
        if (v > best) { best = v; bidx = c; }
    }

    __shared__ float svals[BLOCK_T];
    __shared__ int   sidx[BLOCK_T];
    svals[tid] = best;
    sidx[tid]  = bidx;
    __syncthreads();

    #pragma unroll
    for (int s = BLOCK_T / 2; s > 0; s >>= 1) {
        if (tid < s) {
            float ov = svals[tid + s];
            int   oi = sidx[tid + s];
            if (ov > svals[tid] || (ov == svals[tid] && oi < sidx[tid])) {
                svals[tid] = ov;
                sidx[tid]  = oi;
            }
        }
        __syncthreads();
    }
    const int label = sidx[0];

    // ---- squared distance ||f - c_label||^2, warp 0 only ----
    if (tid < 32) {
        const float* __restrict__ f   = features + (size_t)row * D_DIM;
        const float* __restrict__ cen = centers  + (size_t)label * D_DIM;
        float acc = 0.0f;
        #pragma unroll
        for (int j = 0; j < D_DIM / 32; j++) {
            int d = tid + j * 32;
            float diff = __ldg(f + d) - __ldg(cen + d);
            acc = fmaf(diff, diff, acc);
        }
        #pragma unroll
        for (int off = 16; off > 0; off >>= 1)
            acc += __shfl_down_sync(0xffffffffu, acc, off);
        if (tid == 0) {
            // label column clipped below at EPS; the other C-1 zero entries each
            // clip to EPS and are summed by the reference -> add (C-1)*EPS.
            g_row_loss[row] = fmaxf(acc, EPS_F) + (float)(C_DIM - 1) * EPS_F;
        }
    }
}

__global__ void __launch_bounds__(1024)
center_loss_reduce_kernel(float* __restrict__ out) {
    __shared__ float s[1024];
    const int tid = threadIdx.x;
    float acc = 0.0f;
    #pragma unroll
    for (int i = tid; i < N_ROWS; i += 1024)
        acc += g_row_loss[i];
    s[tid] = acc;
    __syncthreads();
    #pragma unroll
    for (int st = 512; st > 0; st >>= 1) {
        if (tid < st) s[tid] += s[tid + st];
        __syncthreads();
    }
    if (tid == 0) out[0] = s[0] / (float)N_ROWS;
}

extern "C" void kernel_launch(void* const* d_in, const int* in_sizes, int n_in,
                              void* d_out, int out_size) {
    const float* features = (const float*)d_in[0];  // [32,256,96]
    const float* predicts = (const float*)d_in[1];  // [32,256,6625]
    const float* centers  = (const float*)d_in[2];  // [6625,96]
    float* out = (float*)d_out;

    center_loss_row_kernel<<<N_ROWS, BLOCK_T>>>(features, predicts, centers);
    center_loss_reduce_kernel<<<1, 1024>>>(out);
}

// round 3
// speedup vs baseline: 1.1244x; 1.1244x over previous
#include <cuda_runtime.h>
#include <math.h>
#include <stdint.h>

#define C_DIM 6625
#define D_DIM 96
#define N_ROWS 8192
#define EPS_F 1e-7f
#define BLOCK_T 256
#define WARPS_PER_BLOCK (BLOCK_T / 32)
#define GRID_B (N_ROWS / WARPS_PER_BLOCK)   // 1024 blocks, one warp per row

// Scratch (static device allocation — no dynamic alloc allowed).
__device__ float g_row_loss[N_ROWS];
__device__ int   g_done_count = 0;

__global__ void __launch_bounds__(BLOCK_T)
center_loss_fused_kernel(const float* __restrict__ features,
                         const float* __restrict__ predicts,
                         const float* __restrict__ centers,
                         float* __restrict__ out) {
    const int tid  = threadIdx.x;
    const int lane = tid & 31;
    const int warp = tid >> 5;
    const int row  = blockIdx.x * WARPS_PER_BLOCK + warp;

    // ================= per-row argmax over C (warp-collective) =================
    const float* __restrict__ p = predicts + (size_t)row * C_DIM;

    float best = -INFINITY;
    int   bidx = C_DIM;  // sentinel larger than any real index

    // Scalar prologue up to 16B alignment.
    const int mis = (int)(((uintptr_t)p & 15u) >> 2);  // misaligned floats
    const int pro = (4 - mis) & 3;
    if (lane < pro) {
        float v = __ldg(p + lane);
        if (v > best) { best = v; bidx = lane; }
    }

    // Vectorized body: float4, each lane walks ascending indices (first-index
    // tie-break preserved via strict > within a lane, min-idx in the reduce).
    const float4* __restrict__ p4 = (const float4*)(p + pro);
    const int nvec = (C_DIM - pro) >> 2;
    #pragma unroll 8
    for (int i = lane; i < nvec; i += 32) {
        float4 q = __ldg(p4 + i);
        int base = pro + (i << 2);
        if (q.x > best) { best = q.x; bidx = base;     }
        if (q.y > best) { best = q.y; bidx = base + 1; }
        if (q.z > best) { best = q.z; bidx = base + 2; }
        if (q.w > best) { best = q.w; bidx = base + 3; }
    }

    // Scalar tail.
    for (int c = pro + (nvec << 2) + lane; c < C_DIM; c += 32) {
        float v = __ldg(p + c);
        if (v > best) { best = v; bidx = c; }
    }

    // Warp argmax reduce: larger value wins; tie -> smaller index.
    #pragma unroll
    for (int off = 16; off > 0; off >>= 1) {
        float ov = __shfl_down_sync(0xffffffffu, best, off);
        int   oi = __shfl_down_sync(0xffffffffu, bidx, off);
        if (ov > best || (ov == best && oi < bidx)) { best = ov; bidx = oi; }
    }
    const int label = __shfl_sync(0xffffffffu, bidx, 0);

    // ================= squared distance ||f - c_label||^2 =================
    {
        const float* __restrict__ f   = features + (size_t)row * D_DIM;
        const float* __restrict__ cen = centers  + (size_t)label * D_DIM;
        float acc = 0.0f;
        #pragma unroll
        for (int j = 0; j < D_DIM / 32; j++) {
            int d = lane + j * 32;
            float diff = __ldg(f + d) - __ldg(cen + d);
            acc = fmaf(diff, diff, acc);
        }
        #pragma unroll
        for (int off = 16; off > 0; off >>= 1)
            acc += __shfl_down_sync(0xffffffffu, acc, off);
        if (lane == 0) {
            // label column clips at EPS; the C-1 masked-out zeros each clip to
            // EPS and are summed by the reference -> add (C-1)*EPS per row.
            g_row_loss[row] = fmaxf(acc, EPS_F) + (float)(C_DIM - 1) * EPS_F;
        }
    }

    // ================= fused final reduction (last block, fixed order) ========
    __shared__ bool s_is_last;
    __shared__ float s_red[BLOCK_T];

    __threadfence();
    __syncthreads();
    if (tid == 0) {
        int ticket = atomicAdd(&g_done_count, 1);
        s_is_last = (ticket == GRID_B - 1);
    }
    __syncthreads();

    if (s_is_last) {
        // Deterministic: fixed thread->element mapping + fixed tree, regardless
        // of which block ends up running this.
        float acc = 0.0f;
        #pragma unroll
        for (int i = tid; i < N_ROWS; i += BLOCK_T)
            acc += g_row_loss[i];
        s_red[tid] = acc;
        __syncthreads();
        #pragma unroll
        for (int st = BLOCK_T / 2; st > 0; st >>= 1) {
            if (tid < st) s_red[tid] += s_red[tid + st];
            __syncthreads();
        }
        if (tid == 0) {
            out[0] = s_red[0] / (float)N_ROWS;
            g_done_count = 0;  // reset for next graph replay
        }
    }
}

extern "C" void kernel_launch(void* const* d_in, const int* in_sizes, int n_in,
                              void* d_out, int out_size) {
    const float* features = (const float*)d_in[0];  // [32,256,96]
    const float* predicts = (const float*)d_in[1];  // [32,256,6625]
    const float* centers  = (const float*)d_in[2];  // [6625,96]
    float* out = (float*)d_out;

    center_loss_fused_kernel<<<GRID_B, BLOCK_T>>>(features, predicts, centers, out);
}

// round 4
// speedup vs baseline: 1.1339x; 1.0085x over previous
#include <cuda_runtime.h>
#include <math.h>
#include <stdint.h>

#define C_DIM 6625
#define D_DIM 96
#define N_ROWS 8192
#define EPS_F 1e-7f
#define BLOCK_T 256
#define WARPS_PER_BLOCK (BLOCK_T / 32)
#define GRID_B (N_ROWS / WARPS_PER_BLOCK)   // 1024 blocks, one warp per row

// Scratch (static device allocation — no dynamic alloc allowed).
__device__ float g_row_loss[N_ROWS];
__device__ int   g_done_count = 0;

__device__ __forceinline__ float max4(float4 q) {
    return fmaxf(fmaxf(q.x, q.y), fmaxf(q.z, q.w));
}

__global__ void __launch_bounds__(BLOCK_T)
center_loss_fused_kernel(const float* __restrict__ features,
                         const float* __restrict__ predicts,
                         const float* __restrict__ centers,
                         float* __restrict__ out) {
    const int tid  = threadIdx.x;
    const int lane = tid & 31;
    const int warp = tid >> 5;
    const int row  = blockIdx.x * WARPS_PER_BLOCK + warp;

    // ================= per-row argmax over C (warp-collective) =================
    const float* __restrict__ p = predicts + (size_t)row * C_DIM;

    float best = -INFINITY;
    int   bidx = C_DIM;  // sentinel larger than any real index

    // Scalar prologue up to 16B alignment.
    const int mis = (int)(((uintptr_t)p & 15u) >> 2);
    const int pro = (4 - mis) & 3;
    if (lane < pro) {
        float v = __ldg(p + lane);
        if (v > best) { best = v; bidx = lane; }
    }

    const float4* __restrict__ p4 = (const float4*)(p + pro);
    const int nvec  = (C_DIM - pro) >> 2;
    const int nfull = nvec >> 7;           // iterations of 128 vecs (32 lanes x 4)

    int i = lane;                          // vec index for this lane
    for (int it = 0; it < nfull; it++) {
        // --- batch 4 independent 16B loads (front-batched for MLP) ---
        float4 q0 = __ldg(p4 + i);
        float4 q1 = __ldg(p4 + i + 32);
        float4 q2 = __ldg(p4 + i + 64);
        float4 q3 = __ldg(p4 + i + 96);

        // --- branch-free chunk max over 16 values (fmaxf tree) ---
        float m = fmaxf(fmaxf(max4(q0), max4(q1)), fmaxf(max4(q2), max4(q3)));

        // --- rare path: recover first index within chunk (ascending order) ---
        if (m > best) {
            best = m;
            int b0 = pro + (i << 2);
            int b1 = pro + ((i + 32) << 2);
            int b2 = pro + ((i + 64) << 2);
            int b3 = pro + ((i + 96) << 2);
            if      (q0.x == m) bidx = b0;
            else if (q0.y == m) bidx = b0 + 1;
            else if (q0.z == m) bidx = b0 + 2;
            else if (q0.w == m) bidx = b0 + 3;
            else if (q1.x == m) bidx = b1;
            else if (q1.y == m) bidx = b1 + 1;
            else if (q1.z == m) bidx = b1 + 2;
            else if (q1.w == m) bidx = b1 + 3;
            else if (q2.x == m) bidx = b2;
            else if (q2.y == m) bidx = b2 + 1;
            else if (q2.z == m) bidx = b2 + 2;
            else if (q2.w == m) bidx = b2 + 3;
            else if (q3.x == m) bidx = b3;
            else if (q3.y == m) bidx = b3 + 1;
            else if (q3.z == m) bidx = b3 + 2;
            else                bidx = b3 + 3;
        }
        i += 128;
    }

    // Remainder vecs (< 4 per lane).
    for (; i < nvec; i += 32) {
        float4 q = __ldg(p4 + i);
        float m = max4(q);
        if (m > best) {
            best = m;
            int b = pro + (i << 2);
            if      (q.x == m) bidx = b;
            else if (q.y == m) bidx = b + 1;
            else if (q.z == m) bidx = b + 2;
            else               bidx = b + 3;
        }
    }

    // Scalar tail elements.
    for (int c = pro + (nvec << 2) + lane; c < C_DIM; c += 32) {
        float v = __ldg(p + c);
        if (v > best) { best = v; bidx = c; }
    }

    // Warp argmax reduce: larger value wins; tie -> smaller index.
    #pragma unroll
    for (int off = 16; off > 0; off >>= 1) {
        float ov = __shfl_down_sync(0xffffffffu, best, off);
        int   oi = __shfl_down_sync(0xffffffffu, bidx, off);
        if (ov > best || (ov == best && oi < bidx)) { best = ov; bidx = oi; }
    }
    const int label = __shfl_sync(0xffffffffu, bidx, 0);

    // ================= squared distance ||f - c_label||^2 =================
    {
        const float* __restrict__ f   = features + (size_t)row * D_DIM;
        const float* __restrict__ cen = centers  + (size_t)label * D_DIM;
        float acc = 0.0f;
        #pragma unroll
        for (int j = 0; j < D_DIM / 32; j++) {
            int d = lane + j * 32;
            float diff = __ldg(f + d) - __ldg(cen + d);
            acc = fmaf(diff, diff, acc);
        }
        #pragma unroll
        for (int off = 16; off > 0; off >>= 1)
            acc += __shfl_down_sync(0xffffffffu, acc, off);
        if (lane == 0) {
            // label column clips at EPS; the C-1 masked-out zeros each clip to
            // EPS and are summed by the reference -> add (C-1)*EPS per row.
            g_row_loss[row] = fmaxf(acc, EPS_F) + (float)(C_DIM - 1) * EPS_F;
        }
    }

    // ================= fused final reduction (last block, fixed order) ========
    __shared__ bool s_is_last;
    __shared__ float s_red[BLOCK_T];

    __threadfence();
    __syncthreads();
    if (tid == 0) {
        int ticket = atomicAdd(&g_done_count, 1);
        s_is_last = (ticket == GRID_B - 1);
    }
    __syncthreads();

    if (s_is_last) {
        float acc = 0.0f;
        #pragma unroll
        for (int i2 = tid; i2 < N_ROWS; i2 += BLOCK_T)
            acc += g_row_loss[i2];
        s_red[tid] = acc;
        __syncthreads();
        #pragma unroll
        for (int st = BLOCK_T / 2; st > 0; st >>= 1) {
            if (tid < st) s_red[tid] += s_red[tid + st];
            __syncthreads();
        }
        if (tid == 0) {
            out[0] = s_red[0] / (float)N_ROWS;
            g_done_count = 0;  // reset for next graph replay
        }
    }
}

extern "C" void kernel_launch(void* const* d_in, const int* in_sizes, int n_in,
                              void* d_out, int out_size) {
    const float* features = (const float*)d_in[0];  // [32,256,96]
    const float* predicts = (const float*)d_in[1];  // [32,256,6625]
    const float* centers  = (const float*)d_in[2];  // [6625,96]
    float* out = (float*)d_out;

    center_loss_fused_kernel<<<GRID_B, BLOCK_T>>>(features, predicts, centers, out);
}